// round 16
// baseline (speedup 1.0000x reference)
#include <cuda_runtime.h>

// PhotonicMesh: 512-port Clements mesh, 512 layers, 1024 batch rows.
// R16 = R14 skeleton (92us: single-warp CTAs, lane owns 16 ports, register
// ping-pong coef prefetch, branchless odd layer, __launch_bounds__(32,1))
// but each warp carries TWO batch rows sharing one coefficient stream:
//  - L1 wavefront traffic per row HALVES (R14's top constraint at ~65%:
//    17 LDG.128 per warp-iter served 1 row; now 16 serve 2 rows).
//  - ILP doubles (16 independent butterflies) so 3-4 warps/SM suffice.
//  - Cross coefficient recovered by shfl_up of c[15] + lane-0 SEL
//    (coefficients are immutable; saves the extra LDG).
// R1 tried 2 rows/warp and lost ONLY to register spills (capped at 145);
// launch_bounds(32,1) lifts the cap (R13-proven).

#define N_PORT  512
#define N_LAYER 512
#define N_PAIR  256
#define ATTEN_F 0.97723722095581054f   // sqrt(10^(-0.2/10))

// Coefficient table, layout: [(l*8 + k)*32 + lane] where pair p = 8*lane + k.
// Per-k load across a warp is a fully coalesced 512B read.
__device__ float4 g_coef[N_LAYER * N_PAIR];

__global__ void pm_coef_kernel(const float* __restrict__ thetas,
                               const float* __restrict__ phis,
                               const int*   __restrict__ mzi_idx) {
    int l = blockIdx.x;      // layer
    int p = threadIdx.x;     // pair index within layer
    float4 c = make_float4(1.0f, 0.0f, 1.0f, 0.0f);  // identity (unused slots)
    bool odd = (l & 1) != 0;
    bool valid = (!odd) || (p < N_PAIR - 1);         // odd layers have 255 pairs
    if (valid) {
        int i = odd ? (2 * p + 1) : (2 * p);         // upper port of the pair
        int m = mzi_idx[l * N_PORT + i];
        float st, ct, sp, cp;
        sincosf(thetas[m], &st, &ct);
        sincosf(phis[m],   &sp, &cp);
        c = make_float4(ct * ATTEN_F, st * ATTEN_F, cp, sp);
    }
    g_coef[(l * 8 + (p & 7)) * 32 + (p >> 3)] = c;
}

// new_i = e^{i phi}(ct*x_i + st*x_j) ; new_j = ct*x_j - st*x_i
__device__ __forceinline__ void butterfly(float2& xi, float2& xj, float4 c) {
    float ct = c.x, st = c.y, er = c.z, ei = c.w;
    float ur = ct * xi.x + st * xj.x;
    float ui = ct * xi.y + st * xj.y;
    float vr = ct * xj.x - st * xi.x;
    float vi = ct * xj.y - st * xi.y;
    xi.x = er * ur - ei * ui;
    xi.y = er * ui + ei * ur;
    xj.x = vr;
    xj.y = vi;
}

struct CoefBlk { float4 c[16]; };  // [0..7] even pairs, [8..15] odd pairs

__device__ __forceinline__ void load_coefs(CoefBlk& b, int l, int lane) {
    const float4* ce = g_coef + (size_t)l * N_PAIR;
    const float4* co = g_coef + (size_t)(l + 1) * N_PAIR;
    #pragma unroll
    for (int k = 0; k < 8; k++) b.c[k]     = __ldg(&ce[k * 32 + lane]);
    #pragma unroll
    for (int k = 0; k < 8; k++) b.c[k + 8] = __ldg(&co[k * 32 + lane]);
}

// EVEN layer: pairs (16*lane+2k, 16*lane+2k+1), all lane-local.
__device__ __forceinline__ void do_even(float2* s, const float4* c) {
    #pragma unroll
    for (int k = 0; k < 8; k++)
        butterfly(s[2 * k], s[2 * k + 1], c[k]);
}

// ODD layer: local pairs (2k+1, 2k+2) for k=0..6; cross pair via shuffles.
// BRANCH-FREE (R14): lane31's c[7] is identity pair 255 (exact passthrough);
// cx is identity at lane 0 (global port 0). Shfl garbage is killed by *0.
__device__ __forceinline__ void do_odd(float2* s, const float4* c, float2 cx) {
    // snapshot neighbor values BEFORE any update this layer
    float xjr = __shfl_down_sync(0xffffffffu, s[0].x, 1);   // (lane+1).port0
    float xji = __shfl_down_sync(0xffffffffu, s[0].y, 1);
    float xir = __shfl_up_sync(0xffffffffu, s[15].x, 1);    // (lane-1).port15
    float xii = __shfl_up_sync(0xffffffffu, s[15].y, 1);
    #pragma unroll
    for (int k = 0; k < 7; k++)
        butterfly(s[2 * k + 1], s[2 * k + 2], c[k]);
    // cross pair upper port (s15): phase applies
    {
        float ct = c[7].x, st = c[7].y, er = c[7].z, ei = c[7].w;
        float ur = ct * s[15].x + st * xjr;
        float ui = ct * s[15].y + st * xji;
        s[15].x = er * ur - ei * ui;
        s[15].y = er * ui + ei * ur;
    }
    // cross pair lower port (s0): real coefficients
    {
        float2 x0 = s[0];
        s[0].x = cx.x * x0.x - cx.y * xir;
        s[0].y = cx.x * x0.y - cx.y * xii;
    }
}

// lane-1's odd cross-pair (ct, st), identity at lane 0; from c[15] via shfl.
__device__ __forceinline__ float2 cross_coef(const float4& c15, int lane) {
    float ctp = __shfl_up_sync(0xffffffffu, c15.x, 1);
    float stp = __shfl_up_sync(0xffffffffu, c15.y, 1);
    float2 cx;
    cx.x = (lane > 0) ? ctp : 1.0f;
    cx.y = (lane > 0) ? stp : 0.0f;
    return cx;
}

__global__ __launch_bounds__(32, 1)
void pm_mesh_kernel(const float* __restrict__ x, float* __restrict__ out) {
    const int lane = threadIdx.x & 31;
    const int row0 = blockIdx.x * 2;      // this warp's two rows

    float2 sA[16], sB[16];    // complex state of rows row0, row0+1

    // ---- load inputs (real), imag = 0 ----
    const float4* x4 = reinterpret_cast<const float4*>(x);
    #pragma unroll
    for (int v = 0; v < 4; v++) {
        float4 qa = x4[(size_t)row0 * (N_PORT / 4) + lane * 4 + v];
        float4 qb = x4[(size_t)(row0 + 1) * (N_PORT / 4) + lane * 4 + v];
        sA[4 * v + 0] = make_float2(qa.x, 0.f); sB[4 * v + 0] = make_float2(qb.x, 0.f);
        sA[4 * v + 1] = make_float2(qa.y, 0.f); sB[4 * v + 1] = make_float2(qb.y, 0.f);
        sA[4 * v + 2] = make_float2(qa.z, 0.f); sB[4 * v + 2] = make_float2(qb.z, 0.f);
        sA[4 * v + 3] = make_float2(qa.w, 0.f); sB[4 * v + 3] = make_float2(qb.w, 0.f);
    }

    // ---- software-pipelined propagation: ping-pong coefficient buffers ----
    CoefBlk A, B;
    load_coefs(A, 0, lane);

    #pragma unroll 1
    for (int l = 0; l < N_LAYER; l += 4) {
        int ln1 = min(l + 2, N_LAYER - 2);   // tail clamp (result unused)
        load_coefs(B, ln1, lane);
        {
            float2 cx = cross_coef(A.c[15], lane);
            do_even(sA, A.c);        do_even(sB, A.c);
            do_odd (sA, A.c + 8, cx); do_odd (sB, A.c + 8, cx);
        }

        int ln2 = min(l + 4, N_LAYER - 2);   // tail clamp (result unused)
        load_coefs(A, ln2, lane);
        {
            float2 cx = cross_coef(B.c[15], lane);
            do_even(sA, B.c);        do_even(sB, B.c);
            do_odd (sA, B.c + 8, cx); do_odd (sB, B.c + 8, cx);
        }
    }

    // ---- square-law detection + store (both rows) ----
    float4* o4 = reinterpret_cast<float4*>(out);
    #pragma unroll
    for (int v = 0; v < 4; v++) {
        float4 qa, qb;
        qa.x = sA[4 * v + 0].x * sA[4 * v + 0].x + sA[4 * v + 0].y * sA[4 * v + 0].y;
        qa.y = sA[4 * v + 1].x * sA[4 * v + 1].x + sA[4 * v + 1].y * sA[4 * v + 1].y;
        qa.z = sA[4 * v + 2].x * sA[4 * v + 2].x + sA[4 * v + 2].y * sA[4 * v + 2].y;
        qa.w = sA[4 * v + 3].x * sA[4 * v + 3].x + sA[4 * v + 3].y * sA[4 * v + 3].y;
        qb.x = sB[4 * v + 0].x * sB[4 * v + 0].x + sB[4 * v + 0].y * sB[4 * v + 0].y;
        qb.y = sB[4 * v + 1].x * sB[4 * v + 1].x + sB[4 * v + 1].y * sB[4 * v + 1].y;
        qb.z = sB[4 * v + 2].x * sB[4 * v + 2].x + sB[4 * v + 2].y * sB[4 * v + 2].y;
        qb.w = sB[4 * v + 3].x * sB[4 * v + 3].x + sB[4 * v + 3].y * sB[4 * v + 3].y;
        o4[(size_t)row0 * (N_PORT / 4) + lane * 4 + v]       = qa;
        o4[(size_t)(row0 + 1) * (N_PORT / 4) + lane * 4 + v] = qb;
    }
}

extern "C" void kernel_launch(void* const* d_in, const int* in_sizes, int n_in,
                              void* d_out, int out_size) {
    const float* x       = (const float*)d_in[0];
    const float* thetas  = (const float*)d_in[1];
    const float* phis    = (const float*)d_in[2];
    // d_in[3] = partner (unused: structure is static)
    const int*   mzi_idx = (const int*)d_in[4];
    // d_in[5] = role (unused: structure is static)
    float* out = (float*)d_out;

    pm_coef_kernel<<<N_LAYER, N_PAIR>>>(thetas, phis, mzi_idx);
    // 512 single-warp CTAs, 2 rows each: ~3.5 warps/SM on 148+ SMs,
    // coefficient L1 traffic amortized over 2 rows.
    pm_mesh_kernel<<<512, 32>>>(x, out);
}

// round 17
// speedup vs baseline: 1.0054x; 1.0054x over previous
#include <cuda_runtime.h>

// PhotonicMesh: 512-port Clements mesh, 512 layers, 1024 batch rows.
// R17 = R14 (92us best: 1024 single-warp CTAs, lane owns 16 ports, register
// ping-pong coef prefetch, branchless odd layer, launch_bounds(32,1)) with
// two fma-pipe/L1 relief changes:
//  (a) Table padded by 4 layers and coefficient loads driven by a MARCHING
//      POINTER (+1024 float4 per 4 layers): kills the min() clamps and
//      l*256 IMAD address math that was stealing FFMA-pipe slots (IMAD
//      shares the fma pipe, rt 2). All 16 LDGs become [ptr + imm].
//  (b) Cross-pair coefficient via shfl_up of c[15] + lane-0 SEL (R16-
//      validated) instead of a 17th LDG: -4 L1 wavefronts per iteration,
//      +2 SHFL on the idle MIO pipe.

#define N_PORT  512
#define N_LAYER 512
#define N_PAIR  256
#define ATTEN_F 0.97723722095581054f   // sqrt(10^(-0.2/10))

// Coefficient table, layout: [(l*8 + k)*32 + lane] where pair p = 8*lane + k.
// Padded by 4 layers: the software pipeline prefetches up to 4 layers past
// the end; that data is loaded but never consumed (loop exits first).
__device__ float4 g_coef[(N_LAYER + 4) * N_PAIR];

__global__ void pm_coef_kernel(const float* __restrict__ thetas,
                               const float* __restrict__ phis,
                               const int*   __restrict__ mzi_idx) {
    int l = blockIdx.x;      // layer
    int p = threadIdx.x;     // pair index within layer
    float4 c = make_float4(1.0f, 0.0f, 1.0f, 0.0f);  // identity (unused slots)
    bool odd = (l & 1) != 0;
    bool valid = (!odd) || (p < N_PAIR - 1);         // odd layers have 255 pairs
    if (valid) {
        int i = odd ? (2 * p + 1) : (2 * p);         // upper port of the pair
        int m = mzi_idx[l * N_PORT + i];
        float st, ct, sp, cp;
        sincosf(thetas[m], &st, &ct);
        sincosf(phis[m],   &sp, &cp);
        c = make_float4(ct * ATTEN_F, st * ATTEN_F, cp, sp);
    }
    g_coef[(l * 8 + (p & 7)) * 32 + (p >> 3)] = c;
}

// new_i = e^{i phi}(ct*x_i + st*x_j) ; new_j = ct*x_j - st*x_i
__device__ __forceinline__ void butterfly(float2& xi, float2& xj, float4 c) {
    float ct = c.x, st = c.y, er = c.z, ei = c.w;
    float ur = ct * xi.x + st * xj.x;
    float ui = ct * xi.y + st * xj.y;
    float vr = ct * xj.x - st * xi.x;
    float vi = ct * xj.y - st * xi.y;
    xi.x = er * ur - ei * ui;
    xi.y = er * ui + ei * ur;
    xj.x = vr;
    xj.y = vi;
}

struct CoefBlk { float4 c[16]; };  // [0..7] even pairs, [8..15] odd pairs

// base = g_coef + l*256 + lane : all 16 loads are [base + constant].
__device__ __forceinline__ void load_coefs(CoefBlk& b, const float4* base) {
    #pragma unroll
    for (int k = 0; k < 8; k++) b.c[k]     = __ldg(base + k * 32);
    #pragma unroll
    for (int k = 0; k < 8; k++) b.c[k + 8] = __ldg(base + 256 + k * 32);
}

// EVEN layer: pairs (16*lane+2k, 16*lane+2k+1), all lane-local.
__device__ __forceinline__ void do_even(float2* s, const float4* c) {
    #pragma unroll
    for (int k = 0; k < 8; k++)
        butterfly(s[2 * k], s[2 * k + 1], c[k]);
}

// ODD layer: local pairs (2k+1, 2k+2) for k=0..6; cross pair via shuffles.
// BRANCH-FREE (R14): lane31's c[7] is identity pair 255 (exact passthrough);
// cx is identity at lane 0 (global port 0). Shfl garbage is killed by *0.
__device__ __forceinline__ void do_odd(float2* s, const float4* c, float2 cx) {
    // snapshot neighbor values BEFORE any update this layer
    float xjr = __shfl_down_sync(0xffffffffu, s[0].x, 1);   // (lane+1).port0
    float xji = __shfl_down_sync(0xffffffffu, s[0].y, 1);
    float xir = __shfl_up_sync(0xffffffffu, s[15].x, 1);    // (lane-1).port15
    float xii = __shfl_up_sync(0xffffffffu, s[15].y, 1);
    #pragma unroll
    for (int k = 0; k < 7; k++)
        butterfly(s[2 * k + 1], s[2 * k + 2], c[k]);
    // cross pair upper port (s15): phase applies
    {
        float ct = c[7].x, st = c[7].y, er = c[7].z, ei = c[7].w;
        float ur = ct * s[15].x + st * xjr;
        float ui = ct * s[15].y + st * xji;
        s[15].x = er * ur - ei * ui;
        s[15].y = er * ui + ei * ur;
    }
    // cross pair lower port (s0): real coefficients
    {
        float2 x0 = s[0];
        s[0].x = cx.x * x0.x - cx.y * xir;
        s[0].y = cx.x * x0.y - cx.y * xii;
    }
}

// lane-1's odd cross-pair (ct, st), identity at lane 0; from c[15] via shfl.
__device__ __forceinline__ float2 cross_coef(const float4& c15, int lane) {
    float ctp = __shfl_up_sync(0xffffffffu, c15.x, 1);
    float stp = __shfl_up_sync(0xffffffffu, c15.y, 1);
    float2 cx;
    cx.x = (lane > 0) ? ctp : 1.0f;
    cx.y = (lane > 0) ? stp : 0.0f;
    return cx;
}

__global__ __launch_bounds__(32, 1)
void pm_mesh_kernel(const float* __restrict__ x, float* __restrict__ out) {
    const int lane = threadIdx.x & 31;
    const int row  = blockIdx.x;          // one warp-CTA per batch row

    float2 s[16];             // complex state: lane owns ports 16*lane..16*lane+15

    // ---- load input (real), imag = 0 ----
    const float4* x4 = reinterpret_cast<const float4*>(x);
    #pragma unroll
    for (int v = 0; v < 4; v++) {
        float4 q = x4[(size_t)row * (N_PORT / 4) + lane * 4 + v];
        s[4 * v + 0] = make_float2(q.x, 0.f);
        s[4 * v + 1] = make_float2(q.y, 0.f);
        s[4 * v + 2] = make_float2(q.z, 0.f);
        s[4 * v + 3] = make_float2(q.w, 0.f);
    }

    // ---- software-pipelined propagation: marching-pointer prefetch ----
    CoefBlk A, B;
    const float4* gp = g_coef + lane;     // 2-layer block base, marches +1024
    load_coefs(A, gp);

    #pragma unroll 1
    for (int l = 0; l < N_LAYER; l += 4) {
        load_coefs(B, gp + 512);          // layers l+2, l+3 (pad covers tail)
        {
            float2 cx = cross_coef(A.c[15], lane);
            do_even(s, A.c);
            do_odd (s, A.c + 8, cx);
        }

        load_coefs(A, gp + 1024);         // layers l+4, l+5 (pad covers tail)
        {
            float2 cx = cross_coef(B.c[15], lane);
            do_even(s, B.c);
            do_odd (s, B.c + 8, cx);
        }
        gp += 1024;
    }

    // ---- square-law detection + store ----
    float4* o4 = reinterpret_cast<float4*>(out);
    #pragma unroll
    for (int v = 0; v < 4; v++) {
        float4 q;
        q.x = s[4 * v + 0].x * s[4 * v + 0].x + s[4 * v + 0].y * s[4 * v + 0].y;
        q.y = s[4 * v + 1].x * s[4 * v + 1].x + s[4 * v + 1].y * s[4 * v + 1].y;
        q.z = s[4 * v + 2].x * s[4 * v + 2].x + s[4 * v + 2].y * s[4 * v + 2].y;
        q.w = s[4 * v + 3].x * s[4 * v + 3].x + s[4 * v + 3].y * s[4 * v + 3].y;
        o4[(size_t)row * (N_PORT / 4) + lane * 4 + v] = q;
    }
}

extern "C" void kernel_launch(void* const* d_in, const int* in_sizes, int n_in,
                              void* d_out, int out_size) {
    const float* x       = (const float*)d_in[0];
    const float* thetas  = (const float*)d_in[1];
    const float* phis    = (const float*)d_in[2];
    // d_in[3] = partner (unused: structure is static)
    const int*   mzi_idx = (const int*)d_in[4];
    // d_in[5] = role (unused: structure is static)
    float* out = (float*)d_out;

    pm_coef_kernel<<<N_LAYER, N_PAIR>>>(thetas, phis, mzi_idx);
    // 1024 single-warp CTAs: spread across ALL SMs (~7 per SM on 148+ SMs)
    pm_mesh_kernel<<<1024, 32>>>(x, out);
}